// round 16
// baseline (speedup 1.0000x reference)
#include <cuda_runtime.h>
#include <cuda_fp16.h>
#include <cstdint>

// GlobalAggregator fused v10: persistent CTAs + cp.async double-buffered pipeline.
// CTA = 192 thr (6 warps) = 8 bn/tile = 96 rows = 6 m16 tiles (1/warp).
// Raw fp32 neigh+extra staged via cp.async; A-frags built from fp32 smem;
// agg reads the resident smem tile (no second neigh pass).

#define KK 12
#define DIMD 128
#define BN_TOTAL (128 * 512)
#define TILE_BN 8
#define TILE_R 96
#define NT (BN_TOTAL / TILE_BN)       // 8192 tiles
#define GRID_P 296                    // persistent CTAs (148 SMs x 2)
#define NBSTR 132                     // neigh row stride (floats)
#define EXSTR 128                     // extra row stride (floats)
#define CATSTR 132                    // cat row stride (u32; 128 used)

#define OFF_NB0 0
#define OFF_NB1 (TILE_R * NBSTR)                    // 12672
#define OFF_EX0 (2 * TILE_R * NBSTR)                // 25344
#define OFF_EX1 (OFF_EX0 + TILE_BN * EXSTR)         // 26368
#define OFF_CAT (OFF_EX0 + 2 * TILE_BN * EXSTR)     // 27392
#define OFF_SC  (OFF_CAT + TILE_BN * CATSTR)        // 28448
#define SM_U32  (OFF_SC + TILE_R)                   // 28544
#define SM_BYTES (SM_U32 * 4)                       // 114176

__device__ uint2 g_bfrag1[128 * 32];   // w1 frags, [(nt*8+kt)*32+lane]
__device__ uint2 g_bfrag3[256 * 32];   // w3 frags, [(kt*16+nt)*32+lane]
__device__ float4 g_w1w2[64];          // (w1last pair, w2 pair) per (nt, tg)

__device__ __forceinline__ uint32_t packh(float lo, float hi) {
    uint32_t r;
    asm("cvt.rn.f16x2.f32 %0, %1, %2;" : "=r"(r) : "f"(hi), "f"(lo));
    return r;
}
__device__ __forceinline__ void mma16816h(float c[4],
                                          uint32_t a0, uint32_t a1, uint32_t a2, uint32_t a3,
                                          uint32_t b0, uint32_t b1) {
    asm volatile("mma.sync.aligned.m16n8k16.row.col.f32.f16.f16.f32 "
                 "{%0,%1,%2,%3},{%4,%5,%6,%7},{%8,%9},{%0,%1,%2,%3};"
                 : "+f"(c[0]), "+f"(c[1]), "+f"(c[2]), "+f"(c[3])
                 : "r"(a0), "r"(a1), "r"(a2), "r"(a3), "r"(b0), "r"(b1));
}
__device__ __forceinline__ uint32_t smem_u32(const void* p) {
    uint32_t a;
    asm("{ .reg .u64 t; cvta.to.shared.u64 t, %1; cvt.u32.u64 %0, t; }" : "=r"(a) : "l"(p));
    return a;
}
__device__ __forceinline__ void cp16(uint32_t saddr, const void* gaddr) {
    asm volatile("cp.async.cg.shared.global [%0], [%1], 16;" :: "r"(saddr), "l"(gaddr));
}
__device__ __forceinline__ float lrelu(float x) {
    return fmaxf(x, 0.f) + 0.2f * fminf(x, 0.f);
}

// ---------------- prep: bake B fragments ----------------
__global__ void prep_kernel(const float* __restrict__ w1,
                            const float* __restrict__ w2,
                            const float* __restrict__ w3) {
    int idx = blockIdx.x * 256 + threadIdx.x;
    if (idx < 4096) {
        int gi = idx >> 5, lane = idx & 31;
        int nt = gi >> 3, kt = gi & 7;
        int g = lane >> 2, tg = lane & 3;
        int n = nt * 8 + g, k0 = kt * 16 + tg * 2;
        float v0 = w1[k0 * DIMD + n],       v1 = w1[(k0 + 1) * DIMD + n];
        float v2 = w1[(k0 + 8) * DIMD + n], v3 = w1[(k0 + 9) * DIMD + n];
        g_bfrag1[idx] = make_uint2(packh(v0, v1), packh(v2, v3));
    } else if (idx < 4096 + 8192) {
        int j = idx - 4096;
        int gi = j >> 5, lane = j & 31;
        int kt = gi >> 4, nt = gi & 15;
        int g = lane >> 2, tg = lane & 3;
        int n = nt * 8 + g, k0 = kt * 16 + tg * 2;
        float v0 = w3[k0 * DIMD + n],       v1 = w3[(k0 + 1) * DIMD + n];
        float v2 = w3[(k0 + 8) * DIMD + n], v3 = w3[(k0 + 9) * DIMD + n];
        g_bfrag3[j] = make_uint2(packh(v0, v1), packh(v2, v3));
    } else if (idx < 4096 + 8192 + 64) {
        int t = idx - 4096 - 8192;
        int nt = t >> 2, tq = t & 3;
        int c0 = nt * 8 + tq * 2;
        g_w1w2[t] = make_float4(w1[128 * DIMD + c0], w1[128 * DIMD + c0 + 1],
                                w2[c0], w2[c0 + 1]);
    }
}

// ---------------- fused persistent kernel ----------------
__global__ __launch_bounds__(192, 2) void fused_kernel(
    const float* __restrict__ self_v,
    const float* __restrict__ neigh,
    const float* __restrict__ nw,
    const float* __restrict__ extra,
    float* __restrict__ out)
{
    extern __shared__ __align__(16) float smf[];
    uint32_t* smu = (uint32_t*)smf;
    float* scores_s = smf + OFF_SC;
    uint32_t* cat_h = smu + OFF_CAT;

    const int tid = threadIdx.x, wid = tid >> 5, lane = tid & 31;
    const int g = lane >> 2, tg = lane & 3;
    const uint32_t sb = smem_u32(smf);

    auto prefetch = [&](int tile, int bufsel) {
        uint32_t nboff = sb + (bufsel ? OFF_NB1 : OFF_NB0) * 4;
        uint32_t exoff = sb + (bufsel ? OFF_EX1 : OFF_EX0) * 4;
        const char* ng = (const char*)(neigh + (size_t)tile * TILE_R * DIMD);
        const char* eg = (const char*)(extra + (size_t)tile * TILE_BN * DIMD);
#pragma unroll
        for (int j = 0; j < 16; j++) {
            int c = tid + j * 192;
            int row = c >> 5, col = c & 31;
            cp16(nboff + (unsigned)(row * NBSTR + col * 4) * 4, ng + (size_t)c * 16);
        }
        if (tid < 64) {
            int c = tid + 192;
            int row = c >> 5, col = c & 31;
            cp16(exoff + (unsigned)(row * EXSTR + col * 4) * 4, eg + (size_t)c * 16);
        }
        {
            int c = tid;
            int row = c >> 5, col = c & 31;
            cp16(exoff + (unsigned)(row * EXSTR + col * 4) * 4, eg + (size_t)c * 16);
        }
    };

    prefetch(blockIdx.x, 0);
    asm volatile("cp.async.commit_group;" ::: "memory");

    int buf = 0;
    for (int tile = blockIdx.x; tile < NT; tile += GRID_P) {
        int nxt = tile + GRID_P;
        if (nxt < NT) prefetch(nxt, buf ^ 1);
        asm volatile("cp.async.commit_group;" ::: "memory");
        asm volatile("cp.async.wait_group 1;" ::: "memory");
        __syncthreads();

        const float* nbf = smf + (buf ? OFF_NB1 : OFF_NB0);
        const float* exf = smf + (buf ? OFF_EX1 : OFF_EX0);

        // ---- gemm1 (one m16 tile per warp)
        {
            uint32_t A[8][4];
            const int r0 = 16 * wid + g, r1 = r0 + 8;
            const int b0 = r0 / KK, b1 = r1 / KK;
            const float* nb0 = nbf + r0 * NBSTR;
            const float* nb1 = nbf + r1 * NBSTR;
            const float* ex0 = exf + b0 * EXSTR;
            const float* ex1 = exf + b1 * EXSTR;
#pragma unroll
            for (int kt = 0; kt < 8; kt++) {
                int c0 = kt * 16 + 2 * tg, c1 = c0 + 8;
                float2 n00 = *(const float2*)(nb0 + c0);
                float2 e00 = *(const float2*)(ex0 + c0);
                float2 n10 = *(const float2*)(nb1 + c0);
                float2 e10 = *(const float2*)(ex1 + c0);
                float2 n01 = *(const float2*)(nb0 + c1);
                float2 e01 = *(const float2*)(ex0 + c1);
                float2 n11 = *(const float2*)(nb1 + c1);
                float2 e11 = *(const float2*)(ex1 + c1);
                A[kt][0] = packh(n00.x * e00.x, n00.y * e00.y);
                A[kt][1] = packh(n10.x * e10.x, n10.y * e10.y);
                A[kt][2] = packh(n01.x * e01.x, n01.y * e01.y);
                A[kt][3] = packh(n11.x * e11.x, n11.y * e11.y);
            }

            const unsigned gr = (unsigned)tile * TILE_R + r0;
            const float nw0 = __ldg(nw + gr);
            const float nw1 = __ldg(nw + gr + 8);
            float rs0 = 0.f, rs1 = 0.f;

#pragma unroll
            for (int nt0 = 0; nt0 < 16; nt0 += 4) {
                float acc[4][4];
#pragma unroll
                for (int u = 0; u < 4; u++)
#pragma unroll
                    for (int q = 0; q < 4; q++) acc[u][q] = 0.f;
#pragma unroll
                for (int kt = 0; kt < 8; kt++) {
#pragma unroll
                    for (int u = 0; u < 4; u++) {
                        uint2 b = __ldg(&g_bfrag1[((nt0 + u) * 8 + kt) * 32 + lane]);
                        mma16816h(acc[u], A[kt][0], A[kt][1], A[kt][2], A[kt][3], b.x, b.y);
                    }
                }
#pragma unroll
                for (int u = 0; u < 4; u++) {
                    float4 ww = g_w1w2[(nt0 + u) * 4 + tg];
                    float v0 = lrelu(acc[u][0] + nw0 * ww.x);
                    float v1 = lrelu(acc[u][1] + nw0 * ww.y);
                    float v2 = lrelu(acc[u][2] + nw1 * ww.x);
                    float v3 = lrelu(acc[u][3] + nw1 * ww.y);
                    rs0 = fmaf(v0, ww.z, fmaf(v1, ww.w, rs0));
                    rs1 = fmaf(v2, ww.z, fmaf(v3, ww.w, rs1));
                }
            }
            rs0 += __shfl_xor_sync(0xffffffffu, rs0, 1);
            rs0 += __shfl_xor_sync(0xffffffffu, rs0, 2);
            rs1 += __shfl_xor_sync(0xffffffffu, rs1, 1);
            rs1 += __shfl_xor_sync(0xffffffffu, rs1, 2);
            if (tg == 0) {
                scores_s[r0] = rs0;
                scores_s[r1] = rs1;
            }
        }
        __syncthreads();

        // ---- softmax + agg (from resident smem) + cat
        for (int b = wid; b < TILE_BN; b += 6) {
            float alpha[KK];
            {
                float s[KK];
#pragma unroll
                for (int k = 0; k < KK; k++) s[k] = scores_s[b * KK + k];
                float mx = s[0];
#pragma unroll
                for (int k = 1; k < KK; k++) mx = fmaxf(mx, s[k]);
                float tot = 0.f;
#pragma unroll
                for (int k = 0; k < KK; k++) { alpha[k] = __expf(s[k] - mx); tot += alpha[k]; }
                float inv = 1.f / tot;
#pragma unroll
                for (int k = 0; k < KK; k++) alpha[k] *= inv;
            }
            const float4* nb4 = (const float4*)nbf;
            float4 agg = make_float4(0.f, 0.f, 0.f, 0.f);
#pragma unroll
            for (int k = 0; k < KK; k++) {
                float4 v = nb4[(b * KK + k) * (NBSTR / 4) + lane];
                agg.x = fmaf(alpha[k], v.x, agg.x);
                agg.y = fmaf(alpha[k], v.y, agg.y);
                agg.z = fmaf(alpha[k], v.z, agg.z);
                agg.w = fmaf(alpha[k], v.w, agg.w);
            }
            float4 sv = *((const float4*)self_v + (size_t)(tile * TILE_BN + b) * 32 + lane);
            cat_h[b * CATSTR + 2 * lane]          = packh(sv.x, sv.y);
            cat_h[b * CATSTR + 2 * lane + 1]      = packh(sv.z, sv.w);
            cat_h[b * CATSTR + 64 + 2 * lane]     = packh(agg.x, agg.y);
            cat_h[b * CATSTR + 64 + 2 * lane + 1] = packh(agg.z, agg.w);
        }
        __syncthreads();

        // ---- w3 GEMM: 8 bn rows (a1/a3 = 0), 16 nt over 6 warps
        for (int nt = wid; nt < 16; nt += 6) {
            float acc3[4] = {0.f, 0.f, 0.f, 0.f};
#pragma unroll
            for (int kt = 0; kt < 16; kt++) {
                uint32_t a0 = cat_h[g * CATSTR + kt * 8 + tg];
                uint32_t a2 = cat_h[g * CATSTR + kt * 8 + tg + 4];
                uint2 bq = __ldg(&g_bfrag3[(kt * 16 + nt) * 32 + lane]);
                mma16816h(acc3, a0, 0u, a2, 0u, bq.x, bq.y);
            }
            float2 o0 = make_float2(fmaxf(acc3[0], 0.f), fmaxf(acc3[1], 0.f));
            *(float2*)(out + (size_t)(tile * TILE_BN + g) * DIMD + nt * 8 + 2 * tg) = o0;
        }

        buf ^= 1;
    }
}

// ---------------- launch ----------------
extern "C" void kernel_launch(void* const* d_in, const int* in_sizes, int n_in,
                              void* d_out, int out_size) {
    const float* self_v = (const float*)d_in[0];
    const float* neigh  = (const float*)d_in[1];
    const float* nw     = (const float*)d_in[2];
    const float* extra  = (const float*)d_in[3];
    const float* w1     = (const float*)d_in[6];
    const float* w2     = (const float*)d_in[7];
    const float* w3     = (const float*)d_in[8];
    float* out = (float*)d_out;

    static bool attr_set = false;
    if (!attr_set) {
        cudaFuncSetAttribute(fused_kernel, cudaFuncAttributeMaxDynamicSharedMemorySize, SM_BYTES);
        attr_set = true;
    }

    prep_kernel<<<49, 256>>>(w1, w2, w3);
    fused_kernel<<<GRID_P, 192, SM_BYTES>>>(self_v, neigh, nw, extra, out);
}

// round 17
// speedup vs baseline: 1.2428x; 1.2428x over previous
#include <cuda_runtime.h>
#include <cuda_fp16.h>
#include <cstdint>

// GlobalAggregator fused v11: register-resident B fragments.
// CTA = 256 thr (8 warps), 16 bn, 192 rows = 12 m16 tiles.
// Warp owns nt {2w,2w+1}: B in regs (loaded once); loops all 12 A-tiles via
// LDSM. Partial row-scores reduced through smem. Zero LDG in MMA inner loop.

#define KK 12
#define DIMD 128
#define BN_TOTAL (128 * 512)
#define TILE_BN 16
#define TILE_R 192
#define GRID_F (BN_TOTAL / TILE_BN)   // 4096
#define FSTR 68                        // feat row stride in u32 (136 fp16)
#define NWARP 8
#define PSTR 9                         // part row stride (floats), conflict-free

// smem layout (u32 units)
#define OFF_FEAT 0
#define OFF_PART (TILE_R * FSTR)                  // 13056
#define OFF_SC   (OFF_PART + TILE_R * PSTR)       // 14784
#define OFF_CAT  (OFF_SC + TILE_R)                // 14976
#define SM_U32   (OFF_CAT + TILE_BN * 132)        // 17088
#define SM_BYTES (SM_U32 * 4)                     // 68352

__device__ uint2 g_bfrag1[128 * 32];   // w1 frags, [(nt*8+kt)*32+lane]
__device__ uint2 g_bfrag3[256 * 32];   // w3 frags, [(kt*16+nt)*32+lane]
__device__ float4 g_w1w2[64];          // (w1last pair, w2 pair) per (nt, tg)

// ---- helpers ----
__device__ __forceinline__ uint32_t packh(float lo, float hi) {
    uint32_t r;
    asm("cvt.rn.f16x2.f32 %0, %1, %2;" : "=r"(r) : "f"(hi), "f"(lo));
    return r;
}
__device__ __forceinline__ void mma16816h(float c[4],
                                          uint32_t a0, uint32_t a1, uint32_t a2, uint32_t a3,
                                          uint32_t b0, uint32_t b1) {
    asm volatile("mma.sync.aligned.m16n8k16.row.col.f32.f16.f16.f32 "
                 "{%0,%1,%2,%3},{%4,%5,%6,%7},{%8,%9},{%0,%1,%2,%3};"
                 : "+f"(c[0]), "+f"(c[1]), "+f"(c[2]), "+f"(c[3])
                 : "r"(a0), "r"(a1), "r"(a2), "r"(a3), "r"(b0), "r"(b1));
}
__device__ __forceinline__ void ldsm4(uint32_t r[4], uint32_t saddr) {
    asm volatile("ldmatrix.sync.aligned.m8n8.x4.shared.b16 {%0,%1,%2,%3}, [%4];"
                 : "=r"(r[0]), "=r"(r[1]), "=r"(r[2]), "=r"(r[3]) : "r"(saddr));
}
__device__ __forceinline__ uint32_t smem_u32(const void* p) {
    uint32_t a;
    asm("{ .reg .u64 t; cvta.to.shared.u64 t, %1; cvt.u32.u64 %0, t; }" : "=r"(a) : "l"(p));
    return a;
}
__device__ __forceinline__ float lrelu(float x) {
    return fmaxf(x, 0.f) + 0.2f * fminf(x, 0.f);
}

// ---------------- prep: bake B fragments ----------------
__global__ void prep_kernel(const float* __restrict__ w1,
                            const float* __restrict__ w2,
                            const float* __restrict__ w3) {
    int idx = blockIdx.x * 256 + threadIdx.x;
    if (idx < 4096) {                       // w1 frags, [nt][kt] order
        int gi = idx >> 5, lane = idx & 31;
        int nt = gi >> 3, kt = gi & 7;
        int g = lane >> 2, tg = lane & 3;
        int n = nt * 8 + g, k0 = kt * 16 + tg * 2;
        float v0 = w1[k0 * DIMD + n],       v1 = w1[(k0 + 1) * DIMD + n];
        float v2 = w1[(k0 + 8) * DIMD + n], v3 = w1[(k0 + 9) * DIMD + n];
        g_bfrag1[idx] = make_uint2(packh(v0, v1), packh(v2, v3));
    } else if (idx < 4096 + 8192) {         // w3 frags, [kt][nt] order (K=256)
        int j = idx - 4096;
        int gi = j >> 5, lane = j & 31;
        int kt = gi >> 4, nt = gi & 15;
        int g = lane >> 2, tg = lane & 3;
        int n = nt * 8 + g, k0 = kt * 16 + tg * 2;
        float v0 = w3[k0 * DIMD + n],       v1 = w3[(k0 + 1) * DIMD + n];
        float v2 = w3[(k0 + 8) * DIMD + n], v3 = w3[(k0 + 9) * DIMD + n];
        g_bfrag3[j] = make_uint2(packh(v0, v1), packh(v2, v3));
    } else if (idx < 4096 + 8192 + 64) {
        int t = idx - 4096 - 8192;
        int nt = t >> 2, tq = t & 3;
        int c0 = nt * 8 + tq * 2;
        g_w1w2[t] = make_float4(w1[128 * DIMD + c0], w1[128 * DIMD + c0 + 1],
                                w2[c0], w2[c0 + 1]);
    }
}

// ---------------- fused kernel ----------------
__global__ __launch_bounds__(256, 2) void fused_kernel(
    const float* __restrict__ self_v,   // [BN,128]
    const float* __restrict__ neigh,    // [BN,12,128]
    const float* __restrict__ nw,       // [BN,12]
    const float* __restrict__ extra,    // [BN,128]
    float* __restrict__ out)            // [BN,128]
{
    extern __shared__ uint32_t sm[];
    uint32_t* feat = sm + OFF_FEAT;
    float* part = (float*)(sm + OFF_PART);
    float* scores_s = (float*)(sm + OFF_SC);
    uint32_t* cat_h = sm + OFF_CAT;

    const int tid = threadIdx.x, wid = tid >> 5, lane = tid & 31;
    const int g = lane >> 2, tg = lane & 3;
    const int bn0 = blockIdx.x * TILE_BN;
    const unsigned row0 = blockIdx.x * TILE_R;

    // ---- B fragments for this warp's 2 nt, resident in registers
    uint2 b1r[2][8];
    float4 ww[2];
#pragma unroll
    for (int u = 0; u < 2; u++) {
        int nt = 2 * wid + u;
#pragma unroll
        for (int kt = 0; kt < 8; kt++)
            b1r[u][kt] = __ldg(&g_bfrag1[(nt * 8 + kt) * 32 + lane]);
        ww[u] = g_w1w2[nt * 4 + tg];
    }

    // ---- stage feat = neigh * extra (fp16), CTA-cooperative, full unroll
    {
        const float4* ng4 = (const float4*)neigh;
        const float4* ex4 = (const float4*)extra;
#pragma unroll
        for (int r = wid; r < TILE_R; r += NWARP) {
            unsigned gr = row0 + r;
            unsigned bnr = bn0 + r / KK;
            float4 nv = ng4[(size_t)gr * 32 + lane];
            float4 ev = __ldg(ex4 + (size_t)bnr * 32 + lane);
            feat[r * FSTR + 2 * lane]     = packh(nv.x * ev.x, nv.y * ev.y);
            feat[r * FSTR + 2 * lane + 1] = packh(nv.z * ev.z, nv.w * ev.w);
        }
    }
    __syncthreads();

    // ---- gemm1: loop all 12 tiles; A via LDSM; B from registers
    const uint32_t fb = smem_u32(feat);
    const uint32_t acol = (uint32_t)((lane >> 4) * 4);
#pragma unroll 1
    for (int t = 0; t < 12; t++) {
        uint32_t A[8][4];
        {
            uint32_t ridx = (uint32_t)(16 * t + (lane & 15));
#pragma unroll
            for (int kt = 0; kt < 8; kt++)
                ldsm4(A[kt], fb + (ridx * FSTR + kt * 8 + acol) * 4);
        }
        float acc[2][4];
#pragma unroll
        for (int u = 0; u < 2; u++)
#pragma unroll
            for (int q = 0; q < 4; q++) acc[u][q] = 0.f;
#pragma unroll
        for (int kt = 0; kt < 8; kt++) {
            mma16816h(acc[0], A[kt][0], A[kt][1], A[kt][2], A[kt][3],
                      b1r[0][kt].x, b1r[0][kt].y);
            mma16816h(acc[1], A[kt][0], A[kt][1], A[kt][2], A[kt][3],
                      b1r[1][kt].x, b1r[1][kt].y);
        }
        const unsigned gr = row0 + 16 * t + g;
        const float nw0 = __ldg(nw + gr);
        const float nw1 = __ldg(nw + gr + 8);
        float rs0 = 0.f, rs1 = 0.f;
#pragma unroll
        for (int u = 0; u < 2; u++) {
            float v0 = lrelu(acc[u][0] + nw0 * ww[u].x);
            float v1 = lrelu(acc[u][1] + nw0 * ww[u].y);
            float v2 = lrelu(acc[u][2] + nw1 * ww[u].x);
            float v3 = lrelu(acc[u][3] + nw1 * ww[u].y);
            rs0 = fmaf(v0, ww[u].z, fmaf(v1, ww[u].w, rs0));
            rs1 = fmaf(v2, ww[u].z, fmaf(v3, ww[u].w, rs1));
        }
        rs0 += __shfl_xor_sync(0xffffffffu, rs0, 1);
        rs0 += __shfl_xor_sync(0xffffffffu, rs0, 2);
        rs1 += __shfl_xor_sync(0xffffffffu, rs1, 1);
        rs1 += __shfl_xor_sync(0xffffffffu, rs1, 2);
        if (tg == 0) {
            part[(16 * t + g) * PSTR + wid] = rs0;
            part[(16 * t + g + 8) * PSTR + wid] = rs1;
        }
    }
    __syncthreads();

    // ---- reduce partial scores over 8 warps
    if (tid < TILE_R) {
        const float* p = part + tid * PSTR;
        scores_s[tid] = ((p[0] + p[1]) + (p[2] + p[3])) +
                        ((p[4] + p[5]) + (p[6] + p[7]));
    }
    __syncthreads();

    // ---- softmax + agg + cat: 16 bn over 8 warps (agg reload = L2 hit)
    for (int bnl = wid; bnl < TILE_BN; bnl += NWARP) {
        const unsigned gbn = bn0 + bnl;
        float alpha[KK];
        {
            float s[KK];
#pragma unroll
            for (int k = 0; k < KK; k++) s[k] = scores_s[bnl * KK + k];
            float mx = s[0];
#pragma unroll
            for (int k = 1; k < KK; k++) mx = fmaxf(mx, s[k]);
            float tot = 0.f;
#pragma unroll
            for (int k = 0; k < KK; k++) { alpha[k] = __expf(s[k] - mx); tot += alpha[k]; }
            float inv = 1.f / tot;
#pragma unroll
            for (int k = 0; k < KK; k++) alpha[k] *= inv;
        }
        const float4* nb4 = (const float4*)neigh + (size_t)gbn * KK * 32;
        float4 agg = make_float4(0.f, 0.f, 0.f, 0.f);
#pragma unroll
        for (int k = 0; k < KK; k++) {
            float4 v = nb4[k * 32 + lane];
            agg.x = fmaf(alpha[k], v.x, agg.x);
            agg.y = fmaf(alpha[k], v.y, agg.y);
            agg.z = fmaf(alpha[k], v.z, agg.z);
            agg.w = fmaf(alpha[k], v.w, agg.w);
        }
        float4 sv = *((const float4*)self_v + (size_t)gbn * 32 + lane);
        cat_h[bnl * 132 + 2 * lane]          = packh(sv.x, sv.y);
        cat_h[bnl * 132 + 2 * lane + 1]      = packh(sv.z, sv.w);
        cat_h[bnl * 132 + 64 + 2 * lane]     = packh(agg.x, agg.y);
        cat_h[bnl * 132 + 64 + 2 * lane + 1] = packh(agg.z, agg.w);
    }
    __syncthreads();

    // ---- w3 GEMM: one full m16 tile (16 bn), 16 nt over 8 warps (2 each)
#pragma unroll
    for (int v = 0; v < 2; v++) {
        int nt = wid + v * NWARP;
        float acc3[4] = {0.f, 0.f, 0.f, 0.f};
#pragma unroll
        for (int kt = 0; kt < 16; kt++) {
            uint32_t a0 = cat_h[g * 132 + kt * 8 + tg];
            uint32_t a1 = cat_h[(g + 8) * 132 + kt * 8 + tg];
            uint32_t a2 = cat_h[g * 132 + kt * 8 + tg + 4];
            uint32_t a3 = cat_h[(g + 8) * 132 + kt * 8 + tg + 4];
            uint2 bq = __ldg(&g_bfrag3[(kt * 16 + nt) * 32 + lane]);
            mma16816h(acc3, a0, a1, a2, a3, bq.x, bq.y);
        }
        float2 o0 = make_float2(fmaxf(acc3[0], 0.f), fmaxf(acc3[1], 0.f));
        float2 o1 = make_float2(fmaxf(acc3[2], 0.f), fmaxf(acc3[3], 0.f));
        *(float2*)(out + (size_t)(bn0 + g) * DIMD + nt * 8 + 2 * tg) = o0;
        *(float2*)(out + (size_t)(bn0 + g + 8) * DIMD + nt * 8 + 2 * tg) = o1;
    }
}

// ---------------- launch ----------------
extern "C" void kernel_launch(void* const* d_in, const int* in_sizes, int n_in,
                              void* d_out, int out_size) {
    const float* self_v = (const float*)d_in[0];
    const float* neigh  = (const float*)d_in[1];
    const float* nw     = (const float*)d_in[2];
    const float* extra  = (const float*)d_in[3];
    const float* w1     = (const float*)d_in[6];
    const float* w2     = (const float*)d_in[7];
    const float* w3     = (const float*)d_in[8];
    float* out = (float*)d_out;

    static bool attr_set = false;
    if (!attr_set) {
        cudaFuncSetAttribute(fused_kernel, cudaFuncAttributeMaxDynamicSharedMemorySize, SM_BYTES);
        attr_set = true;
    }

    prep_kernel<<<49, 256>>>(w1, w2, w3);
    fused_kernel<<<GRID_F, 256, SM_BYTES>>>(self_v, neigh, nw, extra, out);
}